// round 17
// baseline (speedup 1.0000x reference)
#include <cuda_runtime.h>
#include <math.h>

typedef unsigned long long ull;

#define TPB 224
#define EPB (2 * TPB)   // 448 elements per block

// ---- shared memory float offsets (145392 B -> 1 block/SM) ----
#define W1_OFF    0        // conv1 [pass5][c21][k9][4oc] : 3780
#define W2_OFF    3780     // conv2 [oc][q][32pad] : 2560
#define FC1P_OFF  6340     // fc1 [j1][32] : 3840
#define FC1OH_OFF 10180    // fc1 one-hot cols [j1][8] : 960
#define FC2T_OFF  11140    // fc2 transposed [j1][84] : 10080
#define FC3_OFF   21220    // 84
#define B1_OFF    21304    // 20
#define B2P_OFF   21324    // 32
#define FB1_OFF   21356    // 120
#define FB2_OFF   21476    // 84
#define FB3_OFF   21560    // 1 (+3 pad)
#define STASH_OFF 21564    // per-thread 33-ull stash (stride 33 -> conflict-free 8B)
#define SMEM_FLOATS (STASH_OFF + TPB * 66)   // 36348
#define SMEM_BYTES  (SMEM_FLOATS * 4)        // 145392

__device__ __forceinline__ ull ffma2(ull a, ull b, ull c) {
    ull d; asm("fma.rn.f32x2 %0,%1,%2,%3;" : "=l"(d) : "l"(a), "l"(b), "l"(c)); return d;
}
__device__ __forceinline__ ull pack2(float lo, float hi) {
    ull d; asm("mov.b64 %0,{%1,%2};" : "=l"(d) : "f"(lo), "f"(hi)); return d;
}
__device__ __forceinline__ void unpack2(ull v, float& lo, float& hi) {
    asm("mov.b64 {%0,%1},%2;" : "=f"(lo), "=f"(hi) : "l"(v));
}
__device__ __forceinline__ float lrelu(float v) { return fmaxf(v, 0.2f * v); }

// conv1, ONE channel, 4 oc (2 pairs), BOTH elements: weight loaded once,
// 4 FFMA2 per element per valid tap position.
__device__ __forceinline__ void conv2q(const float* __restrict__ wb,
                                       const ull (&fA)[9], const ull (&fB)[9],
                                       ull (&oA)[2][9], ull (&oB)[2][9]) {
#pragma unroll
    for (int k = 0; k < 9; ++k) {
        const int ky = k / 3, kx = k % 3;
        ulonglong2 w = *reinterpret_cast<const ulonglong2*>(wb + k * 4);
#pragma unroll
        for (int y = 0; y < 3; ++y) {
            const int iy = y + ky - 1;
            if (iy < 0 || iy > 2) continue;
#pragma unroll
            for (int x = 0; x < 3; ++x) {
                const int ix = x + kx - 1;
                if (ix < 0 || ix > 2) continue;
                const int q = y * 3 + x, p = iy * 3 + ix;
                oA[0][q] = ffma2(w.x, fA[p], oA[0][q]);
                oA[1][q] = ffma2(w.y, fA[p], oA[1][q]);
                oB[0][q] = ffma2(w.x, fB[p], oB[0][q]);
                oB[1][q] = ffma2(w.y, fB[p], oB[1][q]);
            }
        }
    }
}

// lrelu + 2x2/s1 maxpool + conv2 accumulate for one conv1 channel (W2 in smem)
__device__ __forceinline__ void poolc2(const float* __restrict__ sm,
                                       float r0, float r1, float r2,
                                       float r3, float r4, float r5,
                                       float r6, float r7, float r8,
                                       int oc, ull (&aa)[16])
{
    r0 = lrelu(r0); r1 = lrelu(r1); r2 = lrelu(r2);
    r3 = lrelu(r3); r4 = lrelu(r4); r5 = lrelu(r5);
    r6 = lrelu(r6); r7 = lrelu(r7); r8 = lrelu(r8);
    float p0 = fmaxf(fmaxf(r0, r1), fmaxf(r3, r4));
    float p1 = fmaxf(fmaxf(r1, r2), fmaxf(r4, r5));
    float p2 = fmaxf(fmaxf(r3, r4), fmaxf(r6, r7));
    float p3 = fmaxf(fmaxf(r4, r5), fmaxf(r7, r8));
#pragma unroll
    for (int q = 0; q < 4; ++q) {
        float pv = (q == 0) ? p0 : (q == 1) ? p1 : (q == 2) ? p2 : p3;
        ull pq = pack2(pv, pv);
        const ulonglong2* wp = reinterpret_cast<const ulonglong2*>(
            sm + W2_OFF + (oc * 4 + q) * 32);
#pragma unroll
        for (int g = 0; g < 8; ++g) {
            ulonglong2 w = wp[g];
            aa[2 * g]     = ffma2(w.x, pq, aa[2 * g]);
            aa[2 * g + 1] = ffma2(w.y, pq, aa[2 * g + 1]);
        }
    }
}

__global__ void __launch_bounds__(TPB, 1)
disc_kernel(const int* __restrict__ state, const int* __restrict__ des,
            const int* __restrict__ act,
            const int* __restrict__ asp, const int* __restrict__ pm,
            const float* __restrict__ path_feature,
            const float* __restrict__ link_feature,
            const float* __restrict__ c1w, const float* __restrict__ c1b,
            const float* __restrict__ c2w, const float* __restrict__ c2b,
            const float* __restrict__ f1w, const float* __restrict__ f1b,
            const float* __restrict__ f2w, const float* __restrict__ f2b,
            const float* __restrict__ f3w, const float* __restrict__ f3b,
            float* __restrict__ out, int B)
{
    extern __shared__ float sm[];
    const int tid = threadIdx.x;

    // ---------- stage + repack weights ----------
    for (int i = tid; i < 3780; i += TPB) {            // W1 [pass][c][k][4]
        int pass = i / 756; int r = i % 756;
        int c = r / 36; int r2 = r % 36;
        int k = r2 / 4; int j = r2 % 4;
        sm[W1_OFF + i] = c1w[((pass * 4 + j) * 21 + c) * 9 + k];
    }
    for (int i = tid; i < 2560; i += TPB) {            // W2 [oc][q][32pad]
        int oc = i / 128; int rem = i % 128; int q = rem / 32; int oc2 = rem % 32;
        sm[W2_OFF + i] = (oc2 < 30) ? c2w[(oc2 * 20 + oc) * 4 + q] : 0.f;
    }
    for (int i = tid; i < 3840; i += TPB) {            // FC1 [j1][32]
        int j = i / 32; int k = i % 32;
        sm[FC1P_OFF + i] = (k < 30) ? f1w[j * 38 + k] : 0.f;
    }
    for (int i = tid; i < 960; i += TPB) {             // FC1 one-hot cols
        int j = i / 8; int a8 = i % 8;
        sm[FC1OH_OFF + i] = f1w[j * 38 + 30 + a8];
    }
    for (int i = tid; i < 10080; i += TPB) {           // FC2 transposed [j1][84]
        int j1 = i / 84; int j2 = i % 84;
        sm[FC2T_OFF + i] = f2w[j2 * 120 + j1];
    }
    for (int i = tid; i < 84; i += TPB) sm[FC3_OFF + i] = f3w[i];
    if (tid < 20) sm[B1_OFF + tid] = c1b[tid];
    if (tid < 32) sm[B2P_OFF + tid] = (tid < 30) ? c2b[tid] : 0.f;
    if (tid < 120) sm[FB1_OFF + tid] = f1b[tid];
    if (tid < 84) sm[FB2_OFF + tid] = f2b[tid];
    if (tid == 0) sm[FB3_OFF] = f3b[0];
    __syncthreads();

    const int e0 = blockIdx.x * EPB + tid;
    const int e1 = e0 + TPB;
    const bool v0 = (e0 < B), v1 = (e1 < B);
    const int bA = v0 ? e0 : (B - 1);
    const int bB = v1 ? e1 : (B - 1);

    const int sA = state[bA], sB = state[bB];
    const int aA = act[bA],   aB = act[bB];
    const float* pbA = path_feature + (size_t)des[bA] * 12;
    const float* pbB = path_feature + (size_t)des[bB] * 12;
    const int* pmA = pm + sA * 9;
    const int* pmB = pm + sB * 9;

    const int NI[9] = {7, 0, 1, 6, 8, 2, 5, 4, 3};
    int nnA[9], nnB[9];
#pragma unroll
    for (int p = 0; p < 9; ++p) {
        nnA[p] = asp[sA * 9 + NI[p]];
        nnB[p] = asp[sB * 9 + NI[p]];
    }

    ull* stash = reinterpret_cast<ull*>(sm + STASH_OFF) + (size_t)tid * 33;

    ull aaA[16], aaB[16];

    // ---------- conv1 in 5 passes of 4 oc, both elements ----------
#pragma unroll 1
    for (int pass = 0; pass < 5; ++pass) {
        const float* wbP = sm + W1_OFF + pass * 756;
        ull oA[2][9], oB[2][9];
        {
            ull b0 = pack2(sm[B1_OFF + 4 * pass],     sm[B1_OFF + 4 * pass + 1]);
            ull b1 = pack2(sm[B1_OFF + 4 * pass + 2], sm[B1_OFF + 4 * pass + 3]);
#pragma unroll
            for (int q = 0; q < 9; ++q) {
                oA[0][q] = b0; oA[1][q] = b1;
                oB[0][q] = b0; oB[1][q] = b1;
            }
        }
        // path channels 0..11 as 6 duos
#pragma unroll 1
        for (int d = 0; d < 6; ++d) {
            float2 gA[9], gB[9];
#pragma unroll
            for (int p = 0; p < 9; ++p) {
                gA[p] = *reinterpret_cast<const float2*>(pbA + (size_t)nnA[p] * 3600 + 2 * d);
                gB[p] = *reinterpret_cast<const float2*>(pbB + (size_t)nnB[p] * 3600 + 2 * d);
            }
            ull fA[9], fB[9];
#pragma unroll
            for (int p = 0; p < 9; ++p) { fA[p] = pack2(gA[p].x, gA[p].x); fB[p] = pack2(gB[p].x, gB[p].x); }
            conv2q(wbP + (2 * d) * 36, fA, fB, oA, oB);
#pragma unroll
            for (int p = 0; p < 9; ++p) { fA[p] = pack2(gA[p].y, gA[p].y); fB[p] = pack2(gB[p].y, gB[p].y); }
            conv2q(wbP + (2 * d + 1) * 36, fA, fB, oA, oB);
        }
        // link channels 12..19 as 4 duos
#pragma unroll 1
        for (int d = 0; d < 4; ++d) {
            float2 gA[9], gB[9];
#pragma unroll
            for (int p = 0; p < 9; ++p) {
                gA[p] = *reinterpret_cast<const float2*>(link_feature + (size_t)nnA[p] * 8 + 2 * d);
                gB[p] = *reinterpret_cast<const float2*>(link_feature + (size_t)nnB[p] * 8 + 2 * d);
            }
            ull fA[9], fB[9];
#pragma unroll
            for (int p = 0; p < 9; ++p) { fA[p] = pack2(gA[p].x, gA[p].x); fB[p] = pack2(gB[p].x, gB[p].x); }
            conv2q(wbP + (12 + 2 * d) * 36, fA, fB, oA, oB);
#pragma unroll
            for (int p = 0; p < 9; ++p) { fA[p] = pack2(gA[p].y, gA[p].y); fB[p] = pack2(gB[p].y, gB[p].y); }
            conv2q(wbP + (12 + 2 * d + 1) * 36, fA, fB, oA, oB);
        }
        // mask channel 20
        {
            ull fA[9], fB[9];
#pragma unroll
            for (int p = 0; p < 9; ++p) {
                float mA = (float)pmA[NI[p]], mB = (float)pmB[NI[p]];
                fA[p] = pack2(mA, mA); fB[p] = pack2(mB, mB);
            }
            conv2q(wbP + 20 * 36, fA, fB, oA, oB);
        }

        // aa: init on pass 0, else restore from stash
        if (pass == 0) {
#pragma unroll
            for (int j = 0; j < 16; ++j) {
                ull bb = pack2(sm[B2P_OFF + 2 * j], sm[B2P_OFF + 2 * j + 1]);
                aaA[j] = bb; aaB[j] = bb;
            }
        } else {
#pragma unroll
            for (int j = 0; j < 16; ++j) { aaA[j] = stash[j]; aaB[j] = stash[16 + j]; }
        }

        // drain: oc 4*pass .. 4*pass+3 for both elements
#pragma unroll
        for (int u = 0; u < 2; ++u) {
            const int oc = 4 * pass + 2 * u;
            float l0,h0,l1,h1,l2,h2,l3,h3,l4,h4,l5,h5,l6,h6,l7,h7,l8,h8;
            unpack2(oA[u][0], l0, h0); unpack2(oA[u][1], l1, h1); unpack2(oA[u][2], l2, h2);
            unpack2(oA[u][3], l3, h3); unpack2(oA[u][4], l4, h4); unpack2(oA[u][5], l5, h5);
            unpack2(oA[u][6], l6, h6); unpack2(oA[u][7], l7, h7); unpack2(oA[u][8], l8, h8);
            poolc2(sm, l0,l1,l2,l3,l4,l5,l6,l7,l8, oc,     aaA);
            poolc2(sm, h0,h1,h2,h3,h4,h5,h6,h7,h8, oc + 1, aaA);
            unpack2(oB[u][0], l0, h0); unpack2(oB[u][1], l1, h1); unpack2(oB[u][2], l2, h2);
            unpack2(oB[u][3], l3, h3); unpack2(oB[u][4], l4, h4); unpack2(oB[u][5], l5, h5);
            unpack2(oB[u][6], l6, h6); unpack2(oB[u][7], l7, h7); unpack2(oB[u][8], l8, h8);
            poolc2(sm, l0,l1,l2,l3,l4,l5,l6,l7,l8, oc,     aaB);
            poolc2(sm, h0,h1,h2,h3,h4,h5,h6,h7,h8, oc + 1, aaB);
        }

        if (pass < 4) {
#pragma unroll
            for (int j = 0; j < 16; ++j) { stash[j] = aaA[j]; stash[16 + j] = aaB[j]; }
        }
    }

    // ---------- fc input ----------
    ull x2A[16], x2B[16];
#pragma unroll
    for (int j = 0; j < 15; ++j) {
        float lo, hi;
        unpack2(aaA[j], lo, hi); x2A[j] = pack2(lrelu(lo), lrelu(hi));
        unpack2(aaB[j], lo, hi); x2B[j] = pack2(lrelu(lo), lrelu(hi));
    }
    x2A[15] = pack2(0.f, 0.f); x2B[15] = pack2(0.f, 0.f);

    float zA = 0.f, zB = 0.f;

    // fc1 (recomputed per half, both elements share weight loads) + fc2 half + fc3 partial
#define FC_HALF2(NH, GBASE, JBASE) { \
    ull hA[NH], hB[NH]; \
    _Pragma("unroll") \
    for (int j = 0; j < (NH); ++j) { \
        ull bb = pack2(sm[FB2_OFF + 2 * ((JBASE) + j)], sm[FB2_OFF + 2 * ((JBASE) + j) + 1]); \
        hA[j] = bb; hB[j] = bb; \
    } \
    _Pragma("unroll 2") \
    for (int j1 = 0; j1 < 120; ++j1) { \
        const ulonglong2* wp = reinterpret_cast<const ulonglong2*>(sm + FC1P_OFF + j1 * 32); \
        ull tA0 = 0ull, tA1 = 0ull, tB0 = 0ull, tB1 = 0ull; \
        _Pragma("unroll") \
        for (int g = 0; g < 4; ++g) { \
            ulonglong2 wA = wp[2 * g], wB = wp[2 * g + 1]; \
            tA0 = ffma2(wA.x, x2A[4 * g],     tA0); \
            tA1 = ffma2(wA.y, x2A[4 * g + 1], tA1); \
            tA0 = ffma2(wB.x, x2A[4 * g + 2], tA0); \
            tA1 = ffma2(wB.y, x2A[4 * g + 3], tA1); \
            tB0 = ffma2(wA.x, x2B[4 * g],     tB0); \
            tB1 = ffma2(wA.y, x2B[4 * g + 1], tB1); \
            tB0 = ffma2(wB.x, x2B[4 * g + 2], tB0); \
            tB1 = ffma2(wB.y, x2B[4 * g + 3], tB1); \
        } \
        float sa0, sa1, sa2, sa3, sb0, sb1, sb2, sb3; \
        unpack2(tA0, sa0, sa1); unpack2(tA1, sa2, sa3); \
        unpack2(tB0, sb0, sb1); unpack2(tB1, sb2, sb3); \
        float fb1 = sm[FB1_OFF + j1]; \
        float tA = fb1 + sm[FC1OH_OFF + j1 * 8 + aA] + ((sa0 + sa1) + (sa2 + sa3)); \
        float tB = fb1 + sm[FC1OH_OFF + j1 * 8 + aB] + ((sb0 + sb1) + (sb2 + sb3)); \
        tA = lrelu(tA); tB = lrelu(tB); \
        ull ttA = pack2(tA, tA), ttB = pack2(tB, tB); \
        const ulonglong2* w2p = reinterpret_cast<const ulonglong2*>(sm + FC2T_OFF + j1 * 84); \
        _Pragma("unroll") \
        for (int g = 0; g < (NH) / 2; ++g) { \
            ulonglong2 w = w2p[(GBASE) + g]; \
            hA[2 * g]     = ffma2(w.x, ttA, hA[2 * g]); \
            hA[2 * g + 1] = ffma2(w.y, ttA, hA[2 * g + 1]); \
            hB[2 * g]     = ffma2(w.x, ttB, hB[2 * g]); \
            hB[2 * g + 1] = ffma2(w.y, ttB, hB[2 * g + 1]); \
        } \
    } \
    _Pragma("unroll") \
    for (int j = 0; j < (NH); ++j) { \
        float w0 = sm[FC3_OFF + 2 * ((JBASE) + j)]; \
        float w1 = sm[FC3_OFF + 2 * ((JBASE) + j) + 1]; \
        float lo, hi; \
        unpack2(hA[j], lo, hi); zA += lrelu(lo) * w0 + lrelu(hi) * w1; \
        unpack2(hB[j], lo, hi); zB += lrelu(lo) * w0 + lrelu(hi) * w1; \
    } }

    FC_HALF2(22, 0,  0)
    FC_HALF2(20, 11, 22)
#undef FC_HALF2

    float fb3 = sm[FB3_OFF];
    if (v0) out[e0] = 1.f / (1.f + expf(-(fb3 + zA)));
    if (v1) out[e1] = 1.f / (1.f + expf(-(fb3 + zB)));
}

extern "C" void kernel_launch(void* const* d_in, const int* in_sizes, int n_in,
                              void* d_out, int out_size)
{
    const int*   state = (const int*)d_in[0];
    const int*   des   = (const int*)d_in[1];
    const int*   act   = (const int*)d_in[2];
    const int*   asp   = (const int*)d_in[3];
    const int*   pm    = (const int*)d_in[4];
    const float* pf    = (const float*)d_in[5];
    const float* lf    = (const float*)d_in[6];
    const float* c1w   = (const float*)d_in[7];
    const float* c1b   = (const float*)d_in[8];
    const float* c2w   = (const float*)d_in[9];
    const float* c2b   = (const float*)d_in[10];
    const float* f1w   = (const float*)d_in[11];
    const float* f1b   = (const float*)d_in[12];
    const float* f2w   = (const float*)d_in[13];
    const float* f2b   = (const float*)d_in[14];
    const float* f3w   = (const float*)d_in[15];
    const float* f3b   = (const float*)d_in[16];

    const int B = in_sizes[0];
    float* out = (float*)d_out;

    cudaFuncSetAttribute(disc_kernel, cudaFuncAttributeMaxDynamicSharedMemorySize, SMEM_BYTES);

    const int grid = (B + EPB - 1) / EPB;   // 147 blocks -> 1 block/SM, single wave
    disc_kernel<<<grid, TPB, SMEM_BYTES>>>(state, des, act, asp, pm, pf, lf,
                                           c1w, c1b, c2w, c2b,
                                           f1w, f1b, f2w, f2b, f3w, f3b,
                                           out, B);
}